// round 8
// baseline (speedup 1.0000x reference)
#include <cuda_runtime.h>
#include <cuda_bf16.h>
#include <cstdint>

// TorchBiRNN: B=64, T=512, I=128, H=256 bidirectional tanh RNN.
// Phase 1: pre[d][t][b][h] = x[b][t][:]·w_ih_d[h][:] + b_ih_d[h] + b_hh_d[h]
// Phase 2: CLUSTERLESS. 128 CTAs, one per (batch,dir). Thread t: c=t&1
//          (k-half), pr=t>>1, rows {pr, pr+128}; w_hh 96 floats/row in regs +
//          32 floats/row streamed from smem. Lane-paired shfl reduction,
//          bank-padded h, ONE __syncthreads per step.

#define OUT_YS (64 * 512 * 512)

__device__ float g_pre[2 * 512 * 64 * 256];   // 64 MB scratch (module-static)

// ---------------- helpers ----------------
__device__ __forceinline__ unsigned long long ffma2(unsigned long long a,
                                                    unsigned long long b,
                                                    unsigned long long c) {
    unsigned long long d;
    asm("fma.rn.f32x2 %0, %1, %2, %3;" : "=l"(d) : "l"(a), "l"(b), "l"(c));
    return d;
}
__device__ __forceinline__ unsigned long long pack2(float a, float b) {
    unsigned long long r;
    asm("mov.b64 %0, {%1, %2};" : "=l"(r) : "f"(a), "f"(b));
    return r;
}
__device__ __forceinline__ float sum2(unsigned long long v) {
    float2 f;
    asm("mov.b64 {%0, %1}, %2;" : "=f"(f.x), "=f"(f.y) : "l"(v));
    return f.x + f.y;
}
__device__ __forceinline__ float fast_tanh(float x) {
    float e = __expf(2.0f * x);
    return 1.0f - __fdividef(2.0f, e + 1.0f);
}

// ---------------------------------------------------------------------------
// Phase 1: GEMM. M=32768 (m = t*64+b), N=256, K=128 staged by 64.
// 64x64 tile, 256 threads, 4x4 microtile, FFMA2, XOR-swizzled smem.
// ---------------------------------------------------------------------------
__global__ __launch_bounds__(256, 2) void pre_gemm_kernel(
    const float* __restrict__ x,
    const float* __restrict__ w_ih_f, const float* __restrict__ b_ih_f,
    const float* __restrict__ b_hh_f,
    const float* __restrict__ w_ih_b, const float* __restrict__ b_ih_b,
    const float* __restrict__ b_hh_b)
{
    __shared__ __align__(16) float4 xs4[64][16];
    __shared__ __align__(16) float4 ws4[64][16];

    const int bx = blockIdx.x;
    const int d  = bx >> 11;
    const int mt = (bx & 2047) >> 2;
    const int nt = bx & 3;
    const float* __restrict__ w_ih = d ? w_ih_b : w_ih_f;
    const float* __restrict__ bi   = d ? b_ih_b : b_ih_f;
    const float* __restrict__ bh   = d ? b_hh_b : b_hh_f;
    const int m0 = mt << 6, n0 = nt << 6;
    const int tid = threadIdx.x;
    const int tm = tid & 15, tn = tid >> 4;

    unsigned long long acc[4][4];
#pragma unroll
    for (int m = 0; m < 4; m++)
#pragma unroll
        for (int n = 0; n < 4; n++) acc[m][n] = 0ull;

#pragma unroll
    for (int ks = 0; ks < 128; ks += 64) {
#pragma unroll
        for (int i = 0; i < 4; i++) {
            int idx = tid + (i << 8);
            int r = idx >> 4, c4 = idx & 15;
            int sw = c4 ^ ((r >> 2) & 7);
            int m = m0 + r;
            int t = m >> 6, b = m & 63;
            xs4[r][sw] = *(const float4*)(x + ((size_t)(b << 9) + t) * 128 + ks + (c4 << 2));
            ws4[r][sw] = *(const float4*)(w_ih + ((size_t)(n0 + r) << 7) + ks + (c4 << 2));
        }
        __syncthreads();
#pragma unroll
        for (int k4 = 0; k4 < 16; k4++) {
            ulonglong2 a2[4], b2[4];
#pragma unroll
            for (int m = 0; m < 4; m++)
                a2[m] = *(const ulonglong2*)&xs4[(tm << 2) + m][k4 ^ (tm & 7)];
#pragma unroll
            for (int n = 0; n < 4; n++)
                b2[n] = *(const ulonglong2*)&ws4[(tn << 2) + n][k4 ^ (tn & 7)];
#pragma unroll
            for (int m = 0; m < 4; m++)
#pragma unroll
                for (int n = 0; n < 4; n++) {
                    acc[m][n] = ffma2(a2[m].x, b2[n].x, acc[m][n]);
                    acc[m][n] = ffma2(a2[m].y, b2[n].y, acc[m][n]);
                }
        }
        __syncthreads();
    }

    const int nbase = n0 + (tn << 2);
    float4 bi4 = *(const float4*)(bi + nbase);
    float4 bh4 = *(const float4*)(bh + nbase);
    float4 bias;
    bias.x = bi4.x + bh4.x; bias.y = bi4.y + bh4.y;
    bias.z = bi4.z + bh4.z; bias.w = bi4.w + bh4.w;

#pragma unroll
    for (int m = 0; m < 4; m++) {
        int mrow = m0 + (tm << 2) + m;
        float4 o;
        o.x = sum2(acc[m][0]) + bias.x;
        o.y = sum2(acc[m][1]) + bias.y;
        o.z = sum2(acc[m][2]) + bias.z;
        o.w = sum2(acc[m][3]) + bias.w;
        *(float4*)(g_pre + ((size_t)(d * 32768 + mrow)) * 256 + nbase) = o;
    }
}

// ---------------------------------------------------------------------------
// Phase 2: recurrence. Grid 128 (one CTA per (batch,dir)), 256 threads.
// Thread t: c = t&1 (k-half), pr = t>>1, rows {pr, pr+128}.
//   k[128c : 128c+96) weights in registers (48 ull per row),
//   k[128c+96 : 128c+128) weights in smem (float4 ws4[c][r2][kq][pr]).
// h per buffer: 260 floats, k>=128 stored at k+4 (bank-decorrelated so the
// warp's two broadcast addresses never collide -> 1 wavefront per h quad).
// Reduction: one shfl.xor(1) between lane pairs. ONE __syncthreads per step.
// Dynamic smem: ws4 65536 | h_buf 2*260*4 = 2080  -> 67616 B.
// ---------------------------------------------------------------------------
__global__ __launch_bounds__(256, 1)
void rnn_step_kernel(const float* __restrict__ w_hh_f,
                     const float* __restrict__ w_hh_b,
                     float* __restrict__ out)
{
    extern __shared__ __align__(16) char smem_raw[];
    float4* ws4   = (float4*)smem_raw;                    // [2][2][8][128]
    float*  h_buf = (float*)(smem_raw + 65536);           // [2][260]

    const int id  = blockIdx.x;
    const int d   = id >> 6;
    const int b   = id & 63;
    const int tid = threadIdx.x;
    const int c   = tid & 1;
    const int pr  = tid >> 1;

    const float* __restrict__ w_hh = d ? w_hh_b : w_hh_f;

    // --- fill smem weights: ws4[((cc*2+r2)*8+kq)*128 + jj] =
    //     w[r2*128+jj][cc*128+96+4kq .. +3]
    for (int i = tid; i < 4096; i += 256) {
        int jj = i & 127, kq = (i >> 7) & 7, r2 = (i >> 10) & 1, cc = i >> 11;
        ws4[i] = *(const float4*)(w_hh + (size_t)((r2 << 7) + jj) * 256
                                       + (cc << 7) + 96 + (kq << 2));
    }

    // --- register weights: rows pr and pr+128, k in [128c, 128c+96)
    unsigned long long w0[48], w1[48];
    {
        const float4* p0 = (const float4*)(w_hh + (size_t)pr * 256 + (c << 7));
        const float4* p1 = (const float4*)(w_hh + (size_t)(pr + 128) * 256 + (c << 7));
#pragma unroll
        for (int q = 0; q < 24; q++) {
            float4 v0 = p0[q], v1 = p1[q];
            w0[2 * q]     = pack2(v0.x, v0.y);
            w0[2 * q + 1] = pack2(v0.z, v0.w);
            w1[2 * q]     = pack2(v1.x, v1.y);
            w1[2 * q + 1] = pack2(v1.z, v1.w);
        }
    }

    // zero initial h (both buffers incl. pads: 520 floats)
    h_buf[tid] = 0.0f;
    h_buf[256 + tid] = 0.0f;
    if (tid < 8) h_buf[512 + tid] = 0.0f;
    __syncthreads();

    const float* pre_base = g_pre + (size_t)d * (512 * 64 * 256);
    const int myrow = c ? (pr + 128) : pr;      // row this thread finishes
    const int mypos = c ? (pr + 132) : pr;      // padded h position
    float pre_cur;
    {
        int t0 = d ? 511 : 0;
        pre_cur = pre_base[((size_t)t0 * 64 + b) * 256 + myrow];
    }

    // streamed-weight bases for this thread (rows pr and pr+128, this c)
    const float4* ws_r0 = ws4 + ((c * 2 + 0) * 8) * 128 + pr;
    const float4* ws_r1 = ws4 + ((c * 2 + 1) * 8) * 128 + pr;
    const int hoff = c ? 132 : 0;               // padded k-half base (floats)

    for (int s = 0; s < 512; s++) {
        const int cur = s & 1, nxt = cur ^ 1;
        const int t = d ? (511 - s) : s;

        // prefetch next pre (LDG in flight across the whole MAC)
        float pre_nxt = 0.0f;
        if (s < 511) {
            int t2 = d ? (510 - s) : (s + 1);
            pre_nxt = pre_base[((size_t)t2 * 64 + b) * 256 + myrow];
        }

        const ulonglong2* hb = (const ulonglong2*)(h_buf + cur * 260 + hoff);

        unsigned long long a0 = 0ull, a1 = 0ull;
        // register-weight part: k-quads 0..23 of this half
#pragma unroll
        for (int q = 0; q < 24; q++) {
            ulonglong2 h2 = hb[q];
            a0 = ffma2(w0[2 * q],     h2.x, a0);
            a0 = ffma2(w0[2 * q + 1], h2.y, a0);
            a1 = ffma2(w1[2 * q],     h2.x, a1);
            a1 = ffma2(w1[2 * q + 1], h2.y, a1);
        }
        // smem-weight part: k-quads 24..31
#pragma unroll
        for (int kq = 0; kq < 8; kq++) {
            ulonglong2 h2 = hb[24 + kq];
            ulonglong2 wv0 = *(const ulonglong2*)&ws_r0[kq * 128];
            ulonglong2 wv1 = *(const ulonglong2*)&ws_r1[kq * 128];
            a0 = ffma2(wv0.x, h2.x, a0);
            a0 = ffma2(wv0.y, h2.y, a0);
            a1 = ffma2(wv1.x, h2.x, a1);
            a1 = ffma2(wv1.y, h2.y, a1);
        }
        float v0 = sum2(a0);   // partial (rowA=pr,     this k-half)
        float v1 = sum2(a1);   // partial (rowB=pr+128, this k-half)

        // lane-pair cross reduction: one shfl — send what the neighbor needs
        float sent = c ? v0 : v1;
        float got  = __shfl_xor_sync(0xffffffffu, sent, 1);
        float v    = (c ? v1 : v0) + got;   // full dot for myrow

        float hv = fast_tanh(v + pre_cur);
        h_buf[nxt * 260 + mypos] = hv;
        out[(((size_t)b << 9) + t) * 512 + (d << 8) + myrow] = hv;
        if (s == 511)
            out[OUT_YS + (((d << 6) + b) << 8) + myrow] = hv;
        pre_cur = pre_nxt;
        __syncthreads();   // publish h[nxt]; all reads of h[cur] done
    }
}

// ---------------------------------------------------------------------------
extern "C" void kernel_launch(void* const* d_in, const int* in_sizes, int n_in,
                              void* d_out, int out_size) {
    const float* x      = (const float*)d_in[0];
    const float* w_ih_f = (const float*)d_in[1];
    const float* w_hh_f = (const float*)d_in[2];
    const float* b_ih_f = (const float*)d_in[3];
    const float* b_hh_f = (const float*)d_in[4];
    const float* w_ih_b = (const float*)d_in[5];
    const float* w_hh_b = (const float*)d_in[6];
    const float* b_ih_b = (const float*)d_in[7];
    const float* b_hh_b = (const float*)d_in[8];
    float* out = (float*)d_out;

    pre_gemm_kernel<<<4096, 256>>>(x, w_ih_f, b_ih_f, b_hh_f,
                                   w_ih_b, b_ih_b, b_hh_b);

    static bool attr_set = false;
    if (!attr_set) {
        cudaFuncSetAttribute(rnn_step_kernel,
                             cudaFuncAttributeMaxDynamicSharedMemorySize, 67616);
        attr_set = true;
    }
    rnn_step_kernel<<<128, 256, 67616>>>(w_hh_f, w_hh_b, out);
}